// round 4
// baseline (speedup 1.0000x reference)
#include <cuda_runtime.h>
#include <cstdint>

// SDF_75806172774865 — R4: cp.async double-buffer + vectorized LDS.128 compute.
// points: (N,P,3) f32 ; v,vn: (N,P,K,3) f32 ; sr: (N,P,K) f32 ; out: (N,) f32
// K fixed at 60: lane sub (0..14) of each 16-lane half handles ks [4*sub,4*sub+4).

#define K_FIX 60
#define SLAB 8                       // points per slab
#define THREADS 128                  // 4 warps, 2 points per warp
#define NWARPS 4
#define ROWF (K_FIX * 3)             // 180 floats per v/vn row
#define V4_SLAB (SLAB * ROWF / 4)    // 360
#define SR4_SLAB (SLAB * K_FIX / 4)  // 120
#define PT4_SLAB (SLAB * 3 / 4)      // 6
#define TOT4 (2 * V4_SLAB + SR4_SLAB + PT4_SLAB)   // 846 float4 per slab
#define BUF_FLOATS (TOT4 * 4)                      // 3384 floats
#define OFF_VN (SLAB * ROWF)         // 1440
#define OFF_SR (2 * SLAB * ROWF)     // 2880
#define OFF_PT (OFF_SR + SLAB * K_FIX) // 3360
#define NMAX 8

__device__ __forceinline__ void cp_async16(void* smem_ptr, const void* gptr) {
    uint32_t sa = (uint32_t)__cvta_generic_to_shared(smem_ptr);
    asm volatile("cp.async.cg.shared.global [%0], [%1], 16;" :: "r"(sa), "l"(gptr));
}
#define CP_COMMIT() asm volatile("cp.async.commit_group;")
#define CP_WAIT1()  asm volatile("cp.async.wait_group 1;")
#define CP_WAIT0()  asm volatile("cp.async.wait_group 0;")

__global__ void sdf_zero_kernel(float* __restrict__ out, int n) {
    int i = blockIdx.x * blockDim.x + threadIdx.x;
    if (i < n) out[i] = 0.0f;
}

__device__ __forceinline__ void stage_slab(
    float* __restrict__ buf,
    const float* __restrict__ v, const float* __restrict__ vn,
    const float* __restrict__ sr, const float* __restrict__ points,
    int slab, int tid, int total_points)
{
    const int gp0 = slab * SLAB;
    const float4* gv  = (const float4*)(v      + (size_t)gp0 * ROWF);
    const float4* gvn = (const float4*)(vn     + (size_t)gp0 * ROWF);
    const float4* gsr = (const float4*)(sr     + (size_t)gp0 * K_FIX);
    const float4* gpt = (const float4*)(points + (size_t)gp0 * 3);
    float4* sv  = (float4*)buf;
    float4* svn = sv  + V4_SLAB;
    float4* ssr = svn + V4_SLAB;
    float4* spt = ssr + SR4_SLAB;

    const int npts = min(SLAB, total_points - gp0);
    if (npts == SLAB) {
        // Fast path: no per-element guards.
        #pragma unroll
        for (int it = 0; it < 7; it++) {
            const int i = tid + it * THREADS;
            if (i < V4_SLAB)                       cp_async16(sv + i, gv + i);
            else if (i < 2 * V4_SLAB)              cp_async16(svn + (i - V4_SLAB), gvn + (i - V4_SLAB));
            else if (i < 2 * V4_SLAB + SR4_SLAB)   cp_async16(ssr + (i - 2 * V4_SLAB), gsr + (i - 2 * V4_SLAB));
            else if (i < TOT4)                     cp_async16(spt + (i - 2 * V4_SLAB - SR4_SLAB),
                                                              gpt + (i - 2 * V4_SLAB - SR4_SLAB));
        }
    } else {
        const int nv4  = npts * (ROWF / 4);
        const int nsr4 = npts * (K_FIX / 4);
        const int npt4 = (npts * 3 + 3) / 4;
        #pragma unroll
        for (int it = 0; it < 7; it++) {
            const int i = tid + it * THREADS;
            if (i < V4_SLAB)                      { if (i < nv4) cp_async16(sv + i, gv + i); }
            else if (i < 2 * V4_SLAB)             { int j = i - V4_SLAB; if (j < nv4) cp_async16(svn + j, gvn + j); }
            else if (i < 2 * V4_SLAB + SR4_SLAB)  { int j = i - 2 * V4_SLAB; if (j < nsr4) cp_async16(ssr + j, gsr + j); }
            else if (i < TOT4)                    { int j = i - 2 * V4_SLAB - SR4_SLAB; if (j < npt4) cp_async16(spt + j, gpt + j); }
        }
    }
}

__device__ __forceinline__ void kstep(float px, float py, float pz,
                                      float vx, float vy, float vz,
                                      float nx, float ny, float nz, float s,
                                      float& num, float& den) {
    const float dx = px - vx;
    const float dy = py - vy;
    const float dz = pz - vz;
    const float d2 = fmaf(dx, dx, fmaf(dy, dy, dz * dz));
    const float w  = 1.0f - d2 * __frcp_rn(s);
    const float w2 = w * w;
    const float phi = (d2 < s) ? (w2 * w2) : 1e-18f;
    const float dot = fmaf(nx, dx, fmaf(ny, dy, nz * dz));
    num = fmaf(phi, dot, num);
    den += phi;
}

__global__ __launch_bounds__(THREADS)
void sdf_kernel(const float* __restrict__ points,
                const float* __restrict__ v,
                const float* __restrict__ vn,
                const float* __restrict__ sr,
                float* __restrict__ out,
                int total_points, int P, int N,
                int total_slabs, int slabs_per_block) {
    __shared__ __align__(16) float s_buf[2][BUF_FLOATS];
    __shared__ float s_acc[NWARPS * NMAX];

    const int tid  = threadIdx.x;
    const int warp = tid >> 5;
    const int lane = tid & 31;
    const int half = lane >> 4;     // 0: point 2w, 1: point 2w+1
    const int sub  = lane & 15;     // 0..14 active in compute

    const int s0 = blockIdx.x * slabs_per_block;
    const int s1 = min(s0 + slabs_per_block, total_slabs);
    if (s0 >= s1) return;

    if (tid < NWARPS * NMAX) s_acc[tid] = 0.0f;

    stage_slab(s_buf[s0 & 1], v, vn, sr, points, s0, tid, total_points);
    CP_COMMIT();

    for (int s = s0; s < s1; s++) {
        const int cur = s & 1;
        __syncthreads();             // compute on buf[cur^1] finished
        if (s + 1 < s1) {
            stage_slab(s_buf[cur ^ 1], v, vn, sr, points, s + 1, tid, total_points);
            CP_COMMIT();
            CP_WAIT1();
        } else {
            CP_WAIT0();
        }
        __syncthreads();

        const float* __restrict__ buf = s_buf[cur];
        const int p  = 2 * warp + half;           // point within slab (0..7)
        const int gp = s * SLAB + p;              // global point
        const bool pvalid = (gp < total_points);

        float num = 0.0f, den = 0.0f;
        if (pvalid && sub < 15) {
            const float* __restrict__ vrow  = buf + p * ROWF;
            const float* __restrict__ vnrow = buf + OFF_VN + p * ROWF;
            const float* __restrict__ srow  = buf + OFF_SR + p * K_FIX;
            const float* __restrict__ prow  = buf + OFF_PT + p * 3;
            const float px = prow[0], py = prow[1], pz = prow[2];

            const float4 va = *(const float4*)(vrow  + sub * 12);
            const float4 vb = *(const float4*)(vrow  + sub * 12 + 4);
            const float4 vc = *(const float4*)(vrow  + sub * 12 + 8);
            const float4 na = *(const float4*)(vnrow + sub * 12);
            const float4 nb = *(const float4*)(vnrow + sub * 12 + 4);
            const float4 nc = *(const float4*)(vnrow + sub * 12 + 8);
            const float4 s4 = *(const float4*)(srow  + sub * 4);

            kstep(px, py, pz, va.x, va.y, va.z, na.x, na.y, na.z, s4.x, num, den);
            kstep(px, py, pz, va.w, vb.x, vb.y, na.w, nb.x, nb.y, s4.y, num, den);
            kstep(px, py, pz, vb.z, vb.w, vc.x, nb.z, nb.w, nc.x, s4.z, num, den);
            kstep(px, py, pz, vc.y, vc.z, vc.w, nc.y, nc.z, nc.w, s4.w, num, den);
        }
        // half-warp (16-lane) reductions: offsets < 16 stay within halves
        #pragma unroll
        for (int o = 8; o > 0; o >>= 1) {
            num += __shfl_xor_sync(0xffffffffu, num, o);
            den += __shfl_xor_sync(0xffffffffu, den, o);
        }
        const float sdf  = num / den;
        const float sdf2 = sdf * sdf;
        const float sdf2B = __shfl_sync(0xffffffffu, sdf2, 16);

        if (lane == 0) {
            const int gpA = s * SLAB + 2 * warp;
            float add = 0.0f;
            const int niA = gpA / P;
            if (gpA < total_points) add += sdf2;
            if (gpA + 1 < total_points) {
                const int niB = (gpA + 1) / P;
                if (niB == niA) add += sdf2B;
                else s_acc[warp * NMAX + niB] += sdf2B;
            }
            s_acc[warp * NMAX + niA] += add;
        }
    }

    __syncthreads();
    if (tid < N && tid < NMAX) {
        float sum = 0.0f;
        #pragma unroll
        for (int w = 0; w < NWARPS; w++) sum += s_acc[w * NMAX + tid];
        atomicAdd(&out[tid], sum);
    }
}

extern "C" void kernel_launch(void* const* d_in, const int* in_sizes, int n_in,
                              void* d_out, int out_size) {
    const float* points = (const float*)d_in[0];
    const float* v      = (const float*)d_in[1];
    const float* vn     = (const float*)d_in[2];
    const float* sr     = (const float*)d_in[3];
    float* out = (float*)d_out;

    const int total_points = in_sizes[0] / 3;  // N*P
    const int N = out_size;
    const int P = total_points / N;

    sdf_zero_kernel<<<1, 32>>>(out, out_size);

    const int total_slabs = (total_points + SLAB - 1) / SLAB;
    const int max_blocks  = 148 * 8;
    const int grid        = total_slabs < max_blocks ? total_slabs : max_blocks;
    const int spb         = (total_slabs + grid - 1) / grid;

    sdf_kernel<<<grid, THREADS>>>(points, v, vn, sr, out,
                                  total_points, P, N, total_slabs, spb);
}